// round 13
// baseline (speedup 1.0000x reference)
#include <cuda_runtime.h>
#include <cstdint>

#define T_STEPS 131072
#define FEATS   8
#define HIDDEN  256
#define BUF     50
#define MAX_K   10
#define BLK     128
#define ROWS    32                     // timesteps per tile
#define NTILES  (T_STEPS / ROWS)       // 4096
#define NBLOCKS 456                    // 3 per SM on 152 SMs
#define SP_N    (ROWS + BUF - 1)       // 81 staged prices
#define DOFF(k) (((k) - 1) * SP_N - (((k) - 1) * (k)) / 2)
#define D_TOTAL (MAX_K * SP_N - (MAX_K * (MAX_K + 1)) / 2)   // 755

// Dynamic smem layout (floats): two tile buffers + aux.
#define OFF_T0    0                          // 32*256 = 8192
#define OFF_T1    (ROWS * HIDDEN)            // 8192
#define OFF_P     (2 * ROWS * HIDDEN)        // 16384
#define OFF_D     (OFF_P + SP_N)
#define OFF_H     (OFF_D + D_TOTAL)
#define OFF_PART  (OFF_H + ROWS)
#define SMEM_FLOATS (OFF_PART + 3 * 5 * ROWS)   // 16384+81+755+32+480 = 17732
#define SMEM_BYTES  ((SMEM_FLOATS * 4 + 127) & ~127)

__device__ __forceinline__ float kconst_log(int k) {
    constexpr float LOGK[11] = {0.f, 0.f, 0.69314718f, 1.09861229f, 1.38629436f,
                                1.60943791f, 1.79175947f, 1.94591015f,
                                2.07944154f, 2.19722458f, 2.30258509f};
    return LOGK[k];
}

// One k's contribution: acc == Lk (scalings folded into compile-time weights).
template<int K>
__device__ __forceinline__ void step_k(const float* __restrict__ s_d, int ts,
        float& c, float& sx, float& sy, float& sxy, float& sxx) {
    const float* __restrict__ dk = s_d + DOFF(K) + ts;
    float acc = 0.0f;
    #pragma unroll
    for (int q = 0; q + K <= BUF - 1; q++) {
        const int   m   = q % K;
        const int   len = (BUF - 1 - m) / K + 1;
        const float wgt = 49.0f / ((float)len * (float)(K * K));
        acc = fmaf(wgt, dk[q], acc);
    }
    if (acc > 0.0f) {
        const float yk = __logf(acc);
        const float xk = kconst_log(K);
        c += 1.0f; sx += xk; sy += yk; sxy += yk * xk; sxx += xk * xk;
    }
}

__global__ __launch_bounds__(BLK)
void fused_hfd_persist_kernel(const float* __restrict__ x,
                              const float* __restrict__ w,
                              const float* __restrict__ b,
                              float* __restrict__ out)
{
    extern __shared__ float smem[];
    float* const s_p    = smem + OFF_P;
    float* const s_d    = smem + OFF_D;
    float* const s_h    = smem + OFF_H;
    float* const s_part = smem + OFF_PART;

    const int tid  = threadIdx.x;
    const int wid  = tid >> 5;
    const int lane = tid & 31;
    const int ts   = lane;                    // local row (32 rows, 4 warps)

    const int j  = tid & 63;                  // float4 column
    const int r0 = tid >> 6;                  // row lane 0..1
    const float4 w4 = __ldg(((const float4*)w) + j);
    const float4 b4 = __ldg(((const float4*)b) + j);

    uint32_t sbase;
    asm volatile("{ .reg .u64 t; cvta.to.shared.u64 t, %1; cvt.u32.u64 %0, t; }"
                 : "=r"(sbase) : "l"(smem));

    for (int tile = blockIdx.x; tile < NTILES; tile += NBLOCKS) {
        const int t0     = tile * ROWS;
        const int base_g = t0 - (BUF - 1);
        const int parity = ((tile / NBLOCKS) & 1);
        float* const s_tile = smem + (parity ? OFF_T1 : OFF_T0);

        // 1) Stage close-price column (coalesced single pass).
        if (tid < SP_N) {
            const int g = base_g + tid;
            s_p[tid] = (g >= 0) ? x[g * FEATS + 3] : 0.0f;
        }
        __syncthreads();

        // 2) Lag-diff tables (one predicated pass per k).
        #pragma unroll
        for (int k = 1; k <= MAX_K; k++) {
            const int n = SP_N - k;           // <= 80 < BLK
            if (tid < n) s_d[DOFF(k) + tid] = fabsf(s_p[tid + k] - s_p[tid]);
        }
        __syncthreads();

        // 3) HFD: 4 warps, one k-subset each; lane = row.
        float c = 0.f, sx = 0.f, sy = 0.f, sxy = 0.f, sxx = 0.f;
        if      (wid == 0) { step_k<1>(s_d, ts, c, sx, sy, sxy, sxx);
                             step_k<5>(s_d, ts, c, sx, sy, sxy, sxx);
                             step_k<9>(s_d, ts, c, sx, sy, sxy, sxx); }
        else if (wid == 1) { step_k<2>(s_d, ts, c, sx, sy, sxy, sxx);
                             step_k<6>(s_d, ts, c, sx, sy, sxy, sxx);
                             step_k<10>(s_d, ts, c, sx, sy, sxy, sxx); }
        else if (wid == 2) { step_k<3>(s_d, ts, c, sx, sy, sxy, sxx);
                             step_k<7>(s_d, ts, c, sx, sy, sxy, sxx); }
        else               { step_k<4>(s_d, ts, c, sx, sy, sxy, sxx);
                             step_k<8>(s_d, ts, c, sx, sy, sxy, sxx); }

        if (wid > 0) {
            float* p = s_part + (wid - 1) * 5 * ROWS;
            p[0 * ROWS + ts] = c;   p[1 * ROWS + ts] = sx;
            p[2 * ROWS + ts] = sy;  p[3 * ROWS + ts] = sxy;
            p[4 * ROWS + ts] = sxx;
        }
        __syncthreads();

        if (wid == 0) {
            #pragma unroll
            for (int q = 0; q < 3; q++) {
                const float* p = s_part + q * 5 * ROWS;
                c   += p[0 * ROWS + ts]; sx  += p[1 * ROWS + ts];
                sy  += p[2 * ROWS + ts]; sxy += p[3 * ROWS + ts];
                sxx += p[4 * ROWS + ts];
            }
            float hfd = 0.0f;
            const float denom = c * sxx - sx * sx;
            if (c > 1.0f && denom != 0.0f)
                hfd = -(c * sxy - sx * sy) / denom;

            // Warmup rows (global t <= 48 -> tiles 0 and 1): growing window.
            const int t = t0 + ts;
            if (t <= BUF - 2) {
                hfd = 0.0f;
                if (t >= MAX_K) {
                    const int   nm1  = t;
                    const float nm1f = (float)nm1;
                    const int   base = -base_g;   // s_p idx of global price[0]
                    float c2=0.f, sx2=0.f, sy2=0.f, sxy2=0.f, sxx2=0.f;
                    for (int k = 1; k <= MAX_K; k++) {
                        float acc = 0.0f;
                        for (int m = 0; m < k; m++) {
                            const int len = (nm1 - m) / k + 1;
                            float s = 0.0f;
                            for (int q = m; q + k <= nm1; q += k)
                                s += fabsf(s_p[base + q + k] - s_p[base + q]);
                            if (len >= 2)
                                acc += s * nm1f / ((float)len * (float)k);
                        }
                        const float Lk = acc / (float)k;
                        if (Lk > 0.0f) {
                            const float yk = __logf(Lk);
                            const float xk = __logf((float)k);
                            c2 += 1.f; sx2 += xk; sy2 += yk;
                            sxy2 += yk * xk; sxx2 += xk * xk;
                        }
                    }
                    const float dn = c2 * sxx2 - sx2 * sx2;
                    if (c2 > 1.0f && dn != 0.0f)
                        hfd = -(c2 * sxy2 - sx2 * sy2) / dn;
                }
            }
            s_h[ts] = hfd;
        }

        // 4) Ensure the buffer we're about to render into has drained
        //    (<=1 outstanding copy == the other buffer's), then render.
        if (tid == 0)
            asm volatile("cp.async.bulk.wait_group.read 1;" ::: "memory");
        __syncthreads();   // also publishes s_h

        float4* const tile4 = (float4*)s_tile;
        #pragma unroll
        for (int rr = 0; rr < ROWS / 2; rr++) {
            const int   row = (rr << 1) | r0;
            const float h   = s_h[row];
            float4 o;
            o.x = fmaxf(fmaf(h, w4.x, b4.x), 0.0f);
            o.y = fmaxf(fmaf(h, w4.y, b4.y), 0.0f);
            o.z = fmaxf(fmaf(h, w4.z, b4.z), 0.0f);
            o.w = fmaxf(fmaf(h, w4.w, b4.w), 0.0f);
            tile4[row * (HIDDEN / 4) + j] = o;
        }
        __syncthreads();

        // 5) Commit async bulk copy of this 32 KB tile; don't wait.
        if (tid == 0) {
            const uint32_t saddr = sbase + (uint32_t)((parity ? OFF_T1 : OFF_T0) * 4);
            asm volatile("fence.proxy.async.shared::cta;" ::: "memory");
            asm volatile("cp.async.bulk.global.shared::cta.bulk_group [%0], [%1], %2;"
                         :: "l"(out + (size_t)t0 * HIDDEN), "r"(saddr),
                            "r"((uint32_t)(ROWS * HIDDEN * 4))
                         : "memory");
            asm volatile("cp.async.bulk.commit_group;" ::: "memory");
        }
        // s_p/s_d overwrite next iteration is safe: all warps passed the
        // render sync, and compute reads happen before it.
    }

    // Drain everything before exit.
    if (tid == 0)
        asm volatile("cp.async.bulk.wait_group.read 0;" ::: "memory");
}

// ---------------------------------------------------------------------------
extern "C" void kernel_launch(void* const* d_in, const int* in_sizes, int n_in,
                              void* d_out, int out_size)
{
    const float* x = (const float*)d_in[0];   // [T, 8]
    const float* w = (const float*)d_in[1];   // [256, 1] -> flat [256]
    const float* b = (const float*)d_in[2];   // [256]
    float* out = (float*)d_out;               // [T, 256] f32

    static bool attr_set = false;
    if (!attr_set) {
        cudaFuncSetAttribute(fused_hfd_persist_kernel,
                             cudaFuncAttributeMaxDynamicSharedMemorySize,
                             SMEM_BYTES);
        attr_set = true;
    }

    fused_hfd_persist_kernel<<<NBLOCKS, BLK, SMEM_BYTES>>>(x, w, b, out);
}

// round 15
// speedup vs baseline: 1.2576x; 1.2576x over previous
#include <cuda_runtime.h>
#include <cstdint>

#define T_STEPS 131072
#define FEATS   8
#define HIDDEN  256
#define BUF     50
#define MAX_K   10
#define BLK     128
#define ROWS    64                     // timesteps per block (2 threads/row)
#define BROWS   48                     // rows written via bulk copy
#define SP_N    (ROWS + BUF - 1)       // 113 staged prices
#define DOFF(k) (((k) - 1) * SP_N - (((k) - 1) * (k)) / 2)
#define D_TOTAL (MAX_K * SP_N - (MAX_K * (MAX_K + 1)) / 2)   // 1075

// Dynamic smem layout (floats)
#define OFF_TILE  0                         // 48*256 = 12288 (bulk region only)
#define OFF_P     (BROWS * HIDDEN)          // 12288
#define OFF_D     (OFF_P + SP_N)
#define OFF_H     (OFF_D + D_TOTAL)
#define OFF_PART  (OFF_H + ROWS)
#define SMEM_FLOATS (OFF_PART + 5 * ROWS)   // 12288+113+1075+64+320 = 13860
#define SMEM_BYTES  ((SMEM_FLOATS * 4 + 127) & ~127)

__device__ __forceinline__ float kconst_log(int k) {
    constexpr float LOGK[11] = {0.f, 0.f, 0.69314718f, 1.09861229f, 1.38629436f,
                                1.60943791f, 1.79175947f, 1.94591015f,
                                2.07944154f, 2.19722458f, 2.30258509f};
    return LOGK[k];
}

template<int HALF>
__device__ __forceinline__ void steady_partial(const float* __restrict__ s_d,
        const int ts, float& c, float& sx, float& sy, float& sxy, float& sxx)
{
    #pragma unroll
    for (int kk = 0; kk < 5; kk++) {
        const int k = 2 * kk + 1 + HALF;
        const float* __restrict__ dk = s_d + DOFF(k) + ts;
        float acc = 0.0f;
        #pragma unroll
        for (int q = 0; q + k <= BUF - 1; q++) {
            const int   m   = q % k;                   // compile-time
            const int   len = (BUF - 1 - m) / k + 1;   // compile-time
            const float wgt = 49.0f / ((float)len * (float)(k * k));
            acc = fmaf(wgt, dk[q], acc);
        }
        if (acc > 0.0f) {
            const float yk = __logf(acc);
            const float xk = kconst_log(k);
            c += 1.0f; sx += xk; sy += yk; sxy += yk * xk; sxx += xk * xk;
        }
    }
}

__global__ __launch_bounds__(BLK)
void fused_hfd_tma_kernel(const float* __restrict__ x,
                          const float* __restrict__ w,
                          const float* __restrict__ b,
                          float* __restrict__ out)
{
    extern __shared__ float smem[];
    float* const s_tile = smem + OFF_TILE;
    float* const s_p    = smem + OFF_P;
    float* const s_d    = smem + OFF_D;
    float* const s_h    = smem + OFF_H;
    float* const s_part = smem + OFF_PART;

    const int t0     = blockIdx.x * ROWS;
    const int base_g = t0 - (BUF - 1);
    const int tid    = threadIdx.x;

    // 1) Stage close-price column (stride 8 floats), coalesced.
    if (tid < SP_N) {
        const int g = base_g + tid;
        s_p[tid] = (g >= 0) ? x[g * FEATS + 3] : 0.0f;
    }
    __syncthreads();

    // 2) Lag-diff tables d_k[i] = |p[i+k]-p[i]| (once per block).
    #pragma unroll
    for (int k = 1; k <= MAX_K; k++) {
        const int n = SP_N - k;            // <= 112 < BLK
        if (tid < n) s_d[DOFF(k) + tid] = fabsf(s_p[tid + k] - s_p[tid]);
    }
    __syncthreads();

    // 3) HFD: warp-parity k-split, 2 threads per row.
    const int wid  = tid >> 5;
    const int lane = tid & 31;
    const int half = wid & 1;
    const int ts   = ((wid >> 1) << 5) | lane;   // local row 0..63

    float c = 0.f, sx = 0.f, sy = 0.f, sxy = 0.f, sxx = 0.f;
    if (half) steady_partial<1>(s_d, ts, c, sx, sy, sxy, sxx);
    else      steady_partial<0>(s_d, ts, c, sx, sy, sxy, sxx);

    if (half) {
        s_part[0 * ROWS + ts] = c;   s_part[1 * ROWS + ts] = sx;
        s_part[2 * ROWS + ts] = sy;  s_part[3 * ROWS + ts] = sxy;
        s_part[4 * ROWS + ts] = sxx;
    }
    __syncthreads();

    if (!half) {
        c   += s_part[0 * ROWS + ts]; sx  += s_part[1 * ROWS + ts];
        sy  += s_part[2 * ROWS + ts]; sxy += s_part[3 * ROWS + ts];
        sxx += s_part[4 * ROWS + ts];

        float hfd = 0.0f;
        const float denom = c * sxx - sx * sx;
        if (c > 1.0f && denom != 0.0f)
            hfd = -(c * sxy - sx * sy) / denom;

        // Block 0 warmup rows (t < 49): growing-window generic path.
        if (blockIdx.x == 0 && ts <= BUF - 2) {
            hfd = 0.0f;
            if (ts >= MAX_K) {
                const int   nm1  = ts;
                const float nm1f = (float)nm1;
                const int   base = BUF - 1;     // s_p index of global price[0]
                float c2=0.f, sx2=0.f, sy2=0.f, sxy2=0.f, sxx2=0.f;
                for (int k = 1; k <= MAX_K; k++) {
                    float acc = 0.0f;
                    for (int m = 0; m < k; m++) {
                        const int len = (nm1 - m) / k + 1;
                        float s = 0.0f;
                        for (int q = m; q + k <= nm1; q += k)
                            s += fabsf(s_p[base + q + k] - s_p[base + q]);
                        if (len >= 2)
                            acc += s * nm1f / ((float)len * (float)k);
                    }
                    const float Lk = acc / (float)k;
                    if (Lk > 0.0f) {
                        const float yk = __logf(Lk);
                        const float xk = __logf((float)k);
                        c2 += 1.f; sx2 += xk; sy2 += yk;
                        sxy2 += yk * xk; sxx2 += xk * xk;
                    }
                }
                const float dn = c2 * sxx2 - sx2 * sx2;
                if (c2 > 1.0f && dn != 0.0f)
                    hfd = -(c2 * sxy2 - sx2 * sy2) / dn;
            }
        }
        s_h[ts] = hfd;
    }
    __syncthreads();

    // 4) Render rows [0, 48) into shared; commit bulk copy ASAP.
    const int j  = tid & 63;                 // float4 column
    const int r0 = tid >> 6;                 // row lane 0..1

    const float4 w4 = __ldg(((const float4*)w) + j);
    const float4 b4 = __ldg(((const float4*)b) + j);

    float4* const tile4 = (float4*)s_tile;
    #pragma unroll
    for (int rr = 0; rr < BROWS / 2; rr++) {
        const int   row = (rr << 1) | r0;
        const float h   = s_h[row];
        float4 o;
        o.x = fmaxf(fmaf(h, w4.x, b4.x), 0.0f);
        o.y = fmaxf(fmaf(h, w4.y, b4.y), 0.0f);
        o.z = fmaxf(fmaf(h, w4.z, b4.z), 0.0f);
        o.w = fmaxf(fmaf(h, w4.w, b4.w), 0.0f);
        tile4[row * (HIDDEN / 4) + j] = o;
    }
    __syncthreads();

    if (tid == 0) {
        uint32_t saddr;
        asm volatile("{ .reg .u64 t; cvta.to.shared.u64 t, %1; cvt.u32.u64 %0, t; }"
                     : "=r"(saddr) : "l"(s_tile));
        asm volatile("fence.proxy.async.shared::cta;" ::: "memory");
        asm volatile("cp.async.bulk.global.shared::cta.bulk_group [%0], [%1], %2;"
                     :: "l"(out + (size_t)t0 * HIDDEN), "r"(saddr),
                        "r"((uint32_t)(BROWS * HIDDEN * 4))
                     : "memory");
        asm volatile("cp.async.bulk.commit_group;" ::: "memory");
    }

    // 5) Rows [48, 64): direct STG while the bulk copy drains behind us.
    float4* const ostg = (float4*)(out + (size_t)t0 * HIDDEN) + j;
    #pragma unroll
    for (int rr = 0; rr < (ROWS - BROWS) / 2; rr++) {
        const int   row = BROWS + ((rr << 1) | r0);
        const float h   = s_h[row];
        float4 o;
        o.x = fmaxf(fmaf(h, w4.x, b4.x), 0.0f);
        o.y = fmaxf(fmaf(h, w4.y, b4.y), 0.0f);
        o.z = fmaxf(fmaf(h, w4.z, b4.z), 0.0f);
        o.w = fmaxf(fmaf(h, w4.w, b4.w), 0.0f);
        ostg[(size_t)row * (HIDDEN / 4)] = o;
    }

    // 6) Drain before smem can be reused by a successor block.
    if (tid == 0)
        asm volatile("cp.async.bulk.wait_group.read 0;" ::: "memory");
}

// ---------------------------------------------------------------------------
extern "C" void kernel_launch(void* const* d_in, const int* in_sizes, int n_in,
                              void* d_out, int out_size)
{
    const float* x = (const float*)d_in[0];   // [T, 8]
    const float* w = (const float*)d_in[1];   // [256, 1] -> flat [256]
    const float* b = (const float*)d_in[2];   // [256]
    float* out = (float*)d_out;               // [T, 256] f32

    static bool attr_set = false;
    if (!attr_set) {
        cudaFuncSetAttribute(fused_hfd_tma_kernel,
                             cudaFuncAttributeMaxDynamicSharedMemorySize,
                             SMEM_BYTES);
        attr_set = true;
    }

    fused_hfd_tma_kernel<<<T_STEPS / ROWS, BLK, SMEM_BYTES>>>(x, w, b, out);
}

// round 16
// speedup vs baseline: 1.3580x; 1.0799x over previous
#include <cuda_runtime.h>
#include <cstdint>

#define T_STEPS 131072
#define FEATS   8
#define HIDDEN  256
#define BUF     50
#define MAX_K   10
#define BLK     128
#define ROWS    64                     // timesteps per block (2 threads/row)
#define SP_N    (ROWS + BUF - 1)       // 113 staged prices
#define DOFF(k) (((k) - 1) * SP_N - (((k) - 1) * (k)) / 2)
#define D_TOTAL (MAX_K * SP_N - (MAX_K * (MAX_K + 1)) / 2)   // 1075

// Dynamic smem layout (floats)
#define OFF_TILE  0                         // 64*256 = 16384
#define OFF_P     (ROWS * HIDDEN)           // 16384
#define OFF_D     (OFF_P + SP_N)            // +113
#define OFF_H     (OFF_D + D_TOTAL)         // +1075
#define OFF_PART  (OFF_H + ROWS)            // +64
#define SMEM_FLOATS (OFF_PART + 5 * ROWS)   // +320 = 17956
#define SMEM_BYTES  ((SMEM_FLOATS * 4 + 127) & ~127)

__device__ __forceinline__ float kconst_log(int k) {
    constexpr float LOGK[11] = {0.f, 0.f, 0.69314718f, 1.09861229f, 1.38629436f,
                                1.60943791f, 1.79175947f, 1.94591015f,
                                2.07944154f, 2.19722458f, 2.30258509f};
    return LOGK[k];
}

template<int HALF>
__device__ __forceinline__ void steady_partial(const float* __restrict__ s_d,
        const int ts, float& c, float& sx, float& sy, float& sxy, float& sxx)
{
    #pragma unroll
    for (int kk = 0; kk < 5; kk++) {
        const int k = 2 * kk + 1 + HALF;
        const float* __restrict__ dk = s_d + DOFF(k) + ts;
        float acc = 0.0f;
        #pragma unroll
        for (int q = 0; q + k <= BUF - 1; q++) {
            const int   m   = q % k;                   // compile-time
            const int   len = (BUF - 1 - m) / k + 1;   // compile-time, >= 4
            const float wgt = 49.0f / ((float)len * (float)(k * k));
            acc = fmaf(wgt, dk[q], acc);
        }
        if (acc > 0.0f) {
            const float yk = __logf(acc);
            const float xk = kconst_log(k);
            c += 1.0f; sx += xk; sy += yk; sxy += yk * xk; sxx += xk * xk;
        }
    }
}

__global__ __launch_bounds__(BLK)
void fused_hfd_tma_kernel(const float* __restrict__ x,
                          const float* __restrict__ w,
                          const float* __restrict__ b,
                          float* __restrict__ out)
{
    extern __shared__ float smem[];
    float* const s_tile = smem + OFF_TILE;
    float* const s_p    = smem + OFF_P;
    float* const s_d    = smem + OFF_D;
    float* const s_h    = smem + OFF_H;
    float* const s_part = smem + OFF_PART;

    const int t0     = blockIdx.x * ROWS;
    const int base_g = t0 - (BUF - 1);
    const int tid    = threadIdx.x;

    // 1) Stage close-price column (stride 8 floats), coalesced.
    if (tid < SP_N) {
        const int g = base_g + tid;
        s_p[tid] = (g >= 0) ? x[g * FEATS + 3] : 0.0f;
    }
    __syncthreads();

    // 2) Lag-diff tables d_k[i] = |p[i+k]-p[i]| (once per block).
    #pragma unroll
    for (int k = 1; k <= MAX_K; k++) {
        const int n = SP_N - k;            // <= 112 < BLK
        if (tid < n) s_d[DOFF(k) + tid] = fabsf(s_p[tid + k] - s_p[tid]);
    }
    __syncthreads();

    // 3) HFD: warp-parity k-split, 2 threads per row.
    const int wid  = tid >> 5;
    const int lane = tid & 31;
    const int half = wid & 1;
    const int ts   = ((wid >> 1) << 5) | lane;   // local row 0..63

    float c = 0.f, sx = 0.f, sy = 0.f, sxy = 0.f, sxx = 0.f;
    if (half) steady_partial<1>(s_d, ts, c, sx, sy, sxy, sxx);
    else      steady_partial<0>(s_d, ts, c, sx, sy, sxy, sxx);

    if (half) {
        s_part[0 * ROWS + ts] = c;   s_part[1 * ROWS + ts] = sx;
        s_part[2 * ROWS + ts] = sy;  s_part[3 * ROWS + ts] = sxy;
        s_part[4 * ROWS + ts] = sxx;
    }
    __syncthreads();

    if (!half) {
        c   += s_part[0 * ROWS + ts]; sx  += s_part[1 * ROWS + ts];
        sy  += s_part[2 * ROWS + ts]; sxy += s_part[3 * ROWS + ts];
        sxx += s_part[4 * ROWS + ts];

        float hfd = 0.0f;
        const float denom = c * sxx - sx * sx;
        if (c > 1.0f && denom != 0.0f)
            hfd = -(c * sxy - sx * sy) / denom;

        // Block 0 warmup rows (t < 49): growing-window generic path.
        if (blockIdx.x == 0 && ts <= BUF - 2) {
            hfd = 0.0f;
            if (ts >= MAX_K) {
                const int   nm1  = ts;
                const float nm1f = (float)nm1;
                const int   base = BUF - 1;     // s_p index of global price[0]
                float c2=0.f, sx2=0.f, sy2=0.f, sxy2=0.f, sxx2=0.f;
                for (int k = 1; k <= MAX_K; k++) {
                    float acc = 0.0f;
                    for (int m = 0; m < k; m++) {
                        const int len = (nm1 - m) / k + 1;
                        float s = 0.0f;
                        for (int q = m; q + k <= nm1; q += k)
                            s += fabsf(s_p[base + q + k] - s_p[base + q]);
                        if (len >= 2)
                            acc += s * nm1f / ((float)len * (float)k);
                    }
                    const float Lk = acc / (float)k;
                    if (Lk > 0.0f) {
                        const float yk = __logf(Lk);
                        const float xk = __logf((float)k);
                        c2 += 1.f; sx2 += xk; sy2 += yk;
                        sxy2 += yk * xk; sxx2 += xk * xk;
                    }
                }
                const float dn = c2 * sxx2 - sx2 * sx2;
                if (c2 > 1.0f && dn != 0.0f)
                    hfd = -(c2 * sxy2 - sx2 * sy2) / dn;
            }
        }
        s_h[ts] = hfd;
    }
    __syncthreads();

    // 4) Render the 64x256 tile into shared memory (STS.128, conflict-free).
    const int j  = tid & 63;                 // float4 column
    const int r0 = tid >> 6;                 // row lane 0..1

    const float4 w4 = __ldg(((const float4*)w) + j);
    const float4 b4 = __ldg(((const float4*)b) + j);

    float4* const tile4 = (float4*)s_tile;
    #pragma unroll 8
    for (int rr = 0; rr < ROWS / 2; rr++) {
        const int   row = (rr << 1) | r0;
        const float h   = s_h[row];
        float4 o;
        o.x = fmaxf(fmaf(h, w4.x, b4.x), 0.0f);
        o.y = fmaxf(fmaf(h, w4.y, b4.y), 0.0f);
        o.z = fmaxf(fmaf(h, w4.z, b4.z), 0.0f);
        o.w = fmaxf(fmaf(h, w4.w, b4.w), 0.0f);
        tile4[row * (HIDDEN / 4) + j] = o;
    }
    __syncthreads();

    // 5) One thread bulk-copies the contiguous 64 KB tile SMEM -> GMEM.
    if (tid == 0) {
        uint32_t saddr;
        asm volatile("{ .reg .u64 t; cvta.to.shared.u64 t, %1; cvt.u32.u64 %0, t; }"
                     : "=r"(saddr) : "l"(s_tile));
        float* const gdst = out + (size_t)t0 * HIDDEN;
        asm volatile("fence.proxy.async.shared::cta;" ::: "memory");
        asm volatile("cp.async.bulk.global.shared::cta.bulk_group [%0], [%1], %2;"
                     :: "l"(gdst), "r"(saddr), "r"((uint32_t)(ROWS * HIDDEN * 4))
                     : "memory");
        asm volatile("cp.async.bulk.commit_group;" ::: "memory");
        asm volatile("cp.async.bulk.wait_group.read 0;" ::: "memory");
    }
    // Block exits only after thread 0's wait completes (smem reuse safety).
}

// ---------------------------------------------------------------------------
extern "C" void kernel_launch(void* const* d_in, const int* in_sizes, int n_in,
                              void* d_out, int out_size)
{
    const float* x = (const float*)d_in[0];   // [T, 8]
    const float* w = (const float*)d_in[1];   // [256, 1] -> flat [256]
    const float* b = (const float*)d_in[2];   // [256]
    float* out = (float*)d_out;               // [T, 256] f32

    static bool attr_set = false;
    if (!attr_set) {
        cudaFuncSetAttribute(fused_hfd_tma_kernel,
                             cudaFuncAttributeMaxDynamicSharedMemorySize,
                             SMEM_BYTES);
        attr_set = true;
    }

    fused_hfd_tma_kernel<<<T_STEPS / ROWS, BLK, SMEM_BYTES>>>(x, w, b, out);
}

// round 17
// speedup vs baseline: 1.3686x; 1.0078x over previous
#include <cuda_runtime.h>
#include <cstdint>

#define T_STEPS 131072
#define FEATS   8
#define HIDDEN  256
#define BUF     50
#define MAX_K   10
#define BLK     128
#define ROWS    64                     // timesteps per block (2 threads/row)
#define HROWS   32                     // rows per copy half
#define SP_N    (ROWS + BUF - 1)       // 113 staged prices
#define DOFF(k) (((k) - 1) * SP_N - (((k) - 1) * (k)) / 2)
#define D_TOTAL (MAX_K * SP_N - (MAX_K * (MAX_K + 1)) / 2)   // 1075

// Dynamic smem layout (floats)
#define OFF_TILE  0                         // 64*256 = 16384
#define OFF_P     (ROWS * HIDDEN)           // 16384
#define OFF_D     (OFF_P + SP_N)            // +113
#define OFF_H     (OFF_D + D_TOTAL)         // +1075
#define OFF_PART  (OFF_H + ROWS)            // +64
#define SMEM_FLOATS (OFF_PART + 5 * ROWS)   // +320 = 17956
#define SMEM_BYTES  ((SMEM_FLOATS * 4 + 127) & ~127)

__device__ __forceinline__ float kconst_log(int k) {
    constexpr float LOGK[11] = {0.f, 0.f, 0.69314718f, 1.09861229f, 1.38629436f,
                                1.60943791f, 1.79175947f, 1.94591015f,
                                2.07944154f, 2.19722458f, 2.30258509f};
    return LOGK[k];
}

template<int HALF>
__device__ __forceinline__ void steady_partial(const float* __restrict__ s_d,
        const int ts, float& c, float& sx, float& sy, float& sxy, float& sxx)
{
    #pragma unroll
    for (int kk = 0; kk < 5; kk++) {
        const int k = 2 * kk + 1 + HALF;
        const float* __restrict__ dk = s_d + DOFF(k) + ts;
        float acc = 0.0f;
        #pragma unroll
        for (int q = 0; q + k <= BUF - 1; q++) {
            const int   m   = q % k;                   // compile-time
            const int   len = (BUF - 1 - m) / k + 1;   // compile-time, >= 4
            const float wgt = 49.0f / ((float)len * (float)(k * k));
            acc = fmaf(wgt, dk[q], acc);
        }
        if (acc > 0.0f) {
            const float yk = __logf(acc);
            const float xk = kconst_log(k);
            c += 1.0f; sx += xk; sy += yk; sxy += yk * xk; sxx += xk * xk;
        }
    }
}

__global__ __launch_bounds__(BLK)
void fused_hfd_tma_kernel(const float* __restrict__ x,
                          const float* __restrict__ w,
                          const float* __restrict__ b,
                          float* __restrict__ out)
{
    extern __shared__ float smem[];
    float* const s_tile = smem + OFF_TILE;
    float* const s_p    = smem + OFF_P;
    float* const s_d    = smem + OFF_D;
    float* const s_h    = smem + OFF_H;
    float* const s_part = smem + OFF_PART;

    const int t0     = blockIdx.x * ROWS;
    const int base_g = t0 - (BUF - 1);
    const int tid    = threadIdx.x;

    // 1) Stage close-price column (stride 8 floats), coalesced.
    if (tid < SP_N) {
        const int g = base_g + tid;
        s_p[tid] = (g >= 0) ? x[g * FEATS + 3] : 0.0f;
    }
    __syncthreads();

    // 2) Lag-diff tables d_k[i] = |p[i+k]-p[i]| (once per block).
    #pragma unroll
    for (int k = 1; k <= MAX_K; k++) {
        const int n = SP_N - k;            // <= 112 < BLK
        if (tid < n) s_d[DOFF(k) + tid] = fabsf(s_p[tid + k] - s_p[tid]);
    }
    __syncthreads();

    // 3) HFD: warp-parity k-split, 2 threads per row.
    const int wid  = tid >> 5;
    const int lane = tid & 31;
    const int half = wid & 1;
    const int ts   = ((wid >> 1) << 5) | lane;   // local row 0..63

    float c = 0.f, sx = 0.f, sy = 0.f, sxy = 0.f, sxx = 0.f;
    if (half) steady_partial<1>(s_d, ts, c, sx, sy, sxy, sxx);
    else      steady_partial<0>(s_d, ts, c, sx, sy, sxy, sxx);

    if (half) {
        s_part[0 * ROWS + ts] = c;   s_part[1 * ROWS + ts] = sx;
        s_part[2 * ROWS + ts] = sy;  s_part[3 * ROWS + ts] = sxy;
        s_part[4 * ROWS + ts] = sxx;
    }
    __syncthreads();

    if (!half) {
        c   += s_part[0 * ROWS + ts]; sx  += s_part[1 * ROWS + ts];
        sy  += s_part[2 * ROWS + ts]; sxy += s_part[3 * ROWS + ts];
        sxx += s_part[4 * ROWS + ts];

        float hfd = 0.0f;
        const float denom = c * sxx - sx * sx;
        if (c > 1.0f && denom != 0.0f)
            hfd = -(c * sxy - sx * sy) / denom;

        // Block 0 warmup rows (t < 49): growing-window generic path.
        if (blockIdx.x == 0 && ts <= BUF - 2) {
            hfd = 0.0f;
            if (ts >= MAX_K) {
                const int   nm1  = ts;
                const float nm1f = (float)nm1;
                const int   base = BUF - 1;     // s_p index of global price[0]
                float c2=0.f, sx2=0.f, sy2=0.f, sxy2=0.f, sxx2=0.f;
                for (int k = 1; k <= MAX_K; k++) {
                    float acc = 0.0f;
                    for (int m = 0; m < k; m++) {
                        const int len = (nm1 - m) / k + 1;
                        float s = 0.0f;
                        for (int q = m; q + k <= nm1; q += k)
                            s += fabsf(s_p[base + q + k] - s_p[base + q]);
                        if (len >= 2)
                            acc += s * nm1f / ((float)len * (float)k);
                    }
                    const float Lk = acc / (float)k;
                    if (Lk > 0.0f) {
                        const float yk = __logf(Lk);
                        const float xk = __logf((float)k);
                        c2 += 1.f; sx2 += xk; sy2 += yk;
                        sxy2 += yk * xk; sxx2 += xk * xk;
                    }
                }
                const float dn = c2 * sxx2 - sx2 * sx2;
                if (c2 > 1.0f && dn != 0.0f)
                    hfd = -(c2 * sxy2 - sx2 * sy2) / dn;
            }
        }
        s_h[ts] = hfd;
    }
    __syncthreads();

    // 4) Render + copy in two 32-row halves; first copy drains behind the
    //    second half's render, so the final wait covers <= 32 KB.
    const int j  = tid & 63;                 // float4 column
    const int r0 = tid >> 6;                 // row lane 0..1

    const float4 w4 = __ldg(((const float4*)w) + j);
    const float4 b4 = __ldg(((const float4*)b) + j);

    float4* const tile4 = (float4*)s_tile;
    uint32_t sbase;
    asm volatile("{ .reg .u64 t; cvta.to.shared.u64 t, %1; cvt.u32.u64 %0, t; }"
                 : "=r"(sbase) : "l"(s_tile));
    float* const gdst = out + (size_t)t0 * HIDDEN;

    #pragma unroll
    for (int hh = 0; hh < 2; hh++) {
        const int rbase = hh * HROWS;
        #pragma unroll 8
        for (int rr = 0; rr < HROWS / 2; rr++) {
            const int   row = rbase + ((rr << 1) | r0);
            const float h   = s_h[row];
            float4 o;
            o.x = fmaxf(fmaf(h, w4.x, b4.x), 0.0f);
            o.y = fmaxf(fmaf(h, w4.y, b4.y), 0.0f);
            o.z = fmaxf(fmaf(h, w4.z, b4.z), 0.0f);
            o.w = fmaxf(fmaf(h, w4.w, b4.w), 0.0f);
            tile4[row * (HIDDEN / 4) + j] = o;
        }
        __syncthreads();
        if (tid == 0) {
            asm volatile("fence.proxy.async.shared::cta;" ::: "memory");
            asm volatile("cp.async.bulk.global.shared::cta.bulk_group [%0], [%1], %2;"
                         :: "l"(gdst + (size_t)rbase * HIDDEN),
                            "r"(sbase + (uint32_t)(rbase * HIDDEN * 4)),
                            "r"((uint32_t)(HROWS * HIDDEN * 4))
                         : "memory");
            asm volatile("cp.async.bulk.commit_group;" ::: "memory");
        }
    }

    // 5) Drain before smem can be reused by a successor block.
    if (tid == 0)
        asm volatile("cp.async.bulk.wait_group.read 0;" ::: "memory");
}

// ---------------------------------------------------------------------------
extern "C" void kernel_launch(void* const* d_in, const int* in_sizes, int n_in,
                              void* d_out, int out_size)
{
    const float* x = (const float*)d_in[0];   // [T, 8]
    const float* w = (const float*)d_in[1];   // [256, 1] -> flat [256]
    const float* b = (const float*)d_in[2];   // [256]
    float* out = (float*)d_out;               // [T, 256] f32

    static bool attr_set = false;
    if (!attr_set) {
        cudaFuncSetAttribute(fused_hfd_tma_kernel,
                             cudaFuncAttributeMaxDynamicSharedMemorySize,
                             SMEM_BYTES);
        attr_set = true;
    }

    fused_hfd_tma_kernel<<<T_STEPS / ROWS, BLK, SMEM_BYTES>>>(x, w, b, out);
}